// round 13
// baseline (speedup 1.0000x reference)
#include <cuda_runtime.h>
#include <cuda_device_runtime_api.h>

// Fused confusion-matrix reduction.
//   y_pred, y_true: [16, 3, 512, 512] f32 -> out [B*C, 4] = [tp, tn, fp, fn]
// tp = sum(p*t); fp = sum(p) - tp; fn = sum(t) - tp; tn = N - sum(p) - sum(t) + tp.
//
// Kernel 1: streaming reduce, 768 CTAs = 16 per slice -> whole grid resident
// in ONE wave (capacity 1184). Bursts of 16 LDG.128 per warp (deeper MLP).
// Early cudaTriggerProgrammaticLaunchCompletion so the PDL finalize is
// scheduled before the reduce finishes.
// Kernel 2: tiny finalize, PDL-launched; waits on grid dependency.

#define SLICES 48                       // B*C
#define N_PER_SLICE (512 * 512)         // 262144 elements per slice
#define BLOCKS_PER_SLICE 16
#define THREADS 256
#define NBLOCKS (SLICES * BLOCKS_PER_SLICE)                       // 768
#define VECS_PER_BLOCK (N_PER_SLICE / BLOCKS_PER_SLICE / 4)       // 4096 float4
#define VECS_PER_THREAD (VECS_PER_BLOCK / THREADS)                // 16
#define OUTER 2
#define INNER 8                          // 8 p-vecs + 8 t-vecs per burst

// Per-block partials: [block][3] = {sum_p, sum_t, sum_pt}.
// Every slot overwritten each launch -> deterministic, graph-replay safe.
__device__ float g_part[NBLOCKS * 3];

__global__ __launch_bounds__(THREADS)
void cm_reduce_kernel(const float4* __restrict__ p4, const float4* __restrict__ t4) {
    const int blk = blockIdx.x;                         // 0 .. 767
    const long base = (long)blk * VECS_PER_BLOCK + threadIdx.x;

    float sp = 0.0f, st = 0.0f, spt = 0.0f;

#pragma unroll 1
    for (int i = 0; i < OUTER; i++) {
        float4 pv[INNER], tv[INNER];
#pragma unroll
        for (int j = 0; j < INNER; j++) {
            const long idx = base + (long)(i * INNER + j) * THREADS;
            pv[j] = __ldg(&p4[idx]);
            tv[j] = __ldg(&t4[idx]);
        }
#pragma unroll
        for (int j = 0; j < INNER; j++) {
            sp  += (pv[j].x + pv[j].y) + (pv[j].z + pv[j].w);
            st  += (tv[j].x + tv[j].y) + (tv[j].z + tv[j].w);
            spt += pv[j].x * tv[j].x + pv[j].y * tv[j].y
                 + pv[j].z * tv[j].z + pv[j].w * tv[j].w;
        }
    }

    // All loads issued & consumed: let the dependent (PDL) grid launch now.
    cudaTriggerProgrammaticLaunchCompletion();

    // Intra-block tree reduction (warp shuffles + smem).
#pragma unroll
    for (int off = 16; off > 0; off >>= 1) {
        sp  += __shfl_down_sync(0xFFFFFFFFu, sp,  off);
        st  += __shfl_down_sync(0xFFFFFFFFu, st,  off);
        spt += __shfl_down_sync(0xFFFFFFFFu, spt, off);
    }

    __shared__ float sm[3][THREADS / 32];
    const int wid = threadIdx.x >> 5;
    const int lid = threadIdx.x & 31;
    if (lid == 0) {
        sm[0][wid] = sp;
        sm[1][wid] = st;
        sm[2][wid] = spt;
    }
    __syncthreads();

    if (threadIdx.x == 0) {
        float a = 0.0f, b = 0.0f, c = 0.0f;
#pragma unroll
        for (int w = 0; w < THREADS / 32; w++) {
            a += sm[0][w];
            b += sm[1][w];
            c += sm[2][w];
        }
        g_part[blk * 3 + 0] = a;
        g_part[blk * 3 + 1] = b;
        g_part[blk * 3 + 2] = c;
    }
}

// Finalize: 768 threads; 16 lanes per slice (one per per-slice block),
// 4-step sub-warp shuffle fold, double only for the final combine.
// PDL: launched alongside the reduce, blocks at the grid dependency sync
// until the reduce's global writes are visible.
#define FIN_THREADS NBLOCKS   // 768
__global__ __launch_bounds__(FIN_THREADS)
void cm_finalize_kernel(float* __restrict__ out) {
    cudaGridDependencySynchronize();

    const int tid = threadIdx.x;                  // 0 .. 767
    const int part = tid & 15;                    // block-within-slice
    const int s = tid >> 4;                       // slice 0 .. 47

    const int idx = (s * BLOCKS_PER_SLICE + part) * 3;
    float a = g_part[idx + 0];
    float b = g_part[idx + 1];
    float c = g_part[idx + 2];

#pragma unroll
    for (int off = 8; off > 0; off >>= 1) {
        a += __shfl_down_sync(0xFFFFFFFFu, a, off, 16);
        b += __shfl_down_sync(0xFFFFFFFFu, b, off, 16);
        c += __shfl_down_sync(0xFFFFFFFFu, c, off, 16);
    }

    if (part == 0) {
        const double da = a, db = b, dc = c;
        const double n = (double)N_PER_SLICE;
        out[s * 4 + 0] = (float)dc;                   // tp
        out[s * 4 + 1] = (float)(n - da - db + dc);   // tn
        out[s * 4 + 2] = (float)(da - dc);            // fp
        out[s * 4 + 3] = (float)(db - dc);            // fn
    }
}

extern "C" void kernel_launch(void* const* d_in, const int* in_sizes, int n_in,
                              void* d_out, int out_size) {
    const float4* p4 = (const float4*)d_in[0];   // y_pred
    const float4* t4 = (const float4*)d_in[1];   // y_true
    float* out = (float*)d_out;

    cm_reduce_kernel<<<NBLOCKS, THREADS>>>(p4, t4);

    // PDL launch of the finalize: overlap its launch latency with the reduce.
    cudaLaunchConfig_t cfg = {};
    cfg.gridDim = dim3(1, 1, 1);
    cfg.blockDim = dim3(FIN_THREADS, 1, 1);
    cfg.dynamicSmemBytes = 0;
    cfg.stream = 0;  // same (captured) default stream as the <<<>>> launch
    cudaLaunchAttribute attrs[1];
    attrs[0].id = cudaLaunchAttributeProgrammaticStreamSerialization;
    attrs[0].val.programmaticStreamSerializationAllowed = 1;
    cfg.attrs = attrs;
    cfg.numAttrs = 1;
    cudaLaunchKernelEx(&cfg, cm_finalize_kernel, out);
}

// round 14
// speedup vs baseline: 1.4569x; 1.4569x over previous
#include <cuda_runtime.h>
#include <cuda_device_runtime_api.h>

// Fused confusion-matrix reduction.
//   y_pred, y_true: [16, 3, 512, 512] f32 -> out [B*C, 4] = [tp, tn, fp, fn]
// tp = sum(p*t); fp = sum(p) - tp; fn = sum(t) - tp; tn = N - sum(p) - sum(t) + tp.
//
// Config measured fastest (R12, 14.8us ~= 6.8 TB/s end-to-end):
//  - 768 CTAs = 16/slice: whole grid resident in ONE wave (capacity ~1184),
//    no straggler wave; 384 starves MLP, 1536 leaves a 352-block tail wave.
//  - Bursts of 8 LDG.128 per warp (OUTER=4 x INNER=4): deeper bursts (16)
//    blow register pressure (64 regs of in-flight float4) and regressed 46%.
//  - NO explicit cudaTriggerProgrammaticLaunchCompletion: the implicit
//    trigger at block end is the only one whose memory-flush covers the
//    g_part stores (an early trigger lets the PDL finalize read stale
//    partials -- latent correctness bug in R13).
//  - Finalize PDL-launched so its startup overlaps the reduce.

#define SLICES 48                       // B*C
#define N_PER_SLICE (512 * 512)         // 262144 elements per slice
#define BLOCKS_PER_SLICE 16
#define THREADS 256
#define NBLOCKS (SLICES * BLOCKS_PER_SLICE)                       // 768
#define VECS_PER_BLOCK (N_PER_SLICE / BLOCKS_PER_SLICE / 4)       // 4096 float4
#define VECS_PER_THREAD (VECS_PER_BLOCK / THREADS)                // 16
#define OUTER 4
#define INNER 4                          // 4 p-vecs + 4 t-vecs per burst

// Per-block partials: [block][3] = {sum_p, sum_t, sum_pt}.
// Every slot overwritten each launch -> deterministic, graph-replay safe.
__device__ float g_part[NBLOCKS * 3];

__global__ __launch_bounds__(THREADS)
void cm_reduce_kernel(const float4* __restrict__ p4, const float4* __restrict__ t4) {
    const int blk = blockIdx.x;                         // 0 .. 767
    const long base = (long)blk * VECS_PER_BLOCK + threadIdx.x;

    float sp = 0.0f, st = 0.0f, spt = 0.0f;

#pragma unroll 1
    for (int i = 0; i < OUTER; i++) {
        float4 pv[INNER], tv[INNER];
#pragma unroll
        for (int j = 0; j < INNER; j++) {
            const long idx = base + (long)(i * INNER + j) * THREADS;
            pv[j] = __ldg(&p4[idx]);
            tv[j] = __ldg(&t4[idx]);
        }
#pragma unroll
        for (int j = 0; j < INNER; j++) {
            sp  += (pv[j].x + pv[j].y) + (pv[j].z + pv[j].w);
            st  += (tv[j].x + tv[j].y) + (tv[j].z + tv[j].w);
            spt += pv[j].x * tv[j].x + pv[j].y * tv[j].y
                 + pv[j].z * tv[j].z + pv[j].w * tv[j].w;
        }
    }

    // Intra-block tree reduction (warp shuffles + smem).
#pragma unroll
    for (int off = 16; off > 0; off >>= 1) {
        sp  += __shfl_down_sync(0xFFFFFFFFu, sp,  off);
        st  += __shfl_down_sync(0xFFFFFFFFu, st,  off);
        spt += __shfl_down_sync(0xFFFFFFFFu, spt, off);
    }

    __shared__ float sm[3][THREADS / 32];
    const int wid = threadIdx.x >> 5;
    const int lid = threadIdx.x & 31;
    if (lid == 0) {
        sm[0][wid] = sp;
        sm[1][wid] = st;
        sm[2][wid] = spt;
    }
    __syncthreads();

    if (threadIdx.x == 0) {
        float a = 0.0f, b = 0.0f, c = 0.0f;
#pragma unroll
        for (int w = 0; w < THREADS / 32; w++) {
            a += sm[0][w];
            b += sm[1][w];
            c += sm[2][w];
        }
        g_part[blk * 3 + 0] = a;
        g_part[blk * 3 + 1] = b;
        g_part[blk * 3 + 2] = c;
    }
}

// Finalize: 768 threads; 16 lanes per slice (one per per-slice block),
// 4-step sub-warp shuffle fold, double only for the final combine.
// PDL: launched alongside the reduce, blocks at the grid dependency sync
// until the reduce's global writes are visible.
#define FIN_THREADS NBLOCKS   // 768
__global__ __launch_bounds__(FIN_THREADS)
void cm_finalize_kernel(float* __restrict__ out) {
    cudaGridDependencySynchronize();

    const int tid = threadIdx.x;                  // 0 .. 767
    const int part = tid & 15;                    // block-within-slice
    const int s = tid >> 4;                       // slice 0 .. 47

    const int idx = (s * BLOCKS_PER_SLICE + part) * 3;
    float a = g_part[idx + 0];
    float b = g_part[idx + 1];
    float c = g_part[idx + 2];

#pragma unroll
    for (int off = 8; off > 0; off >>= 1) {
        a += __shfl_down_sync(0xFFFFFFFFu, a, off, 16);
        b += __shfl_down_sync(0xFFFFFFFFu, b, off, 16);
        c += __shfl_down_sync(0xFFFFFFFFu, c, off, 16);
    }

    if (part == 0) {
        const double da = a, db = b, dc = c;
        const double n = (double)N_PER_SLICE;
        out[s * 4 + 0] = (float)dc;                   // tp
        out[s * 4 + 1] = (float)(n - da - db + dc);   // tn
        out[s * 4 + 2] = (float)(da - dc);            // fp
        out[s * 4 + 3] = (float)(db - dc);            // fn
    }
}

extern "C" void kernel_launch(void* const* d_in, const int* in_sizes, int n_in,
                              void* d_out, int out_size) {
    const float4* p4 = (const float4*)d_in[0];   // y_pred
    const float4* t4 = (const float4*)d_in[1];   // y_true
    float* out = (float*)d_out;

    cm_reduce_kernel<<<NBLOCKS, THREADS>>>(p4, t4);

    // PDL launch of the finalize: overlap its launch latency with the reduce.
    cudaLaunchConfig_t cfg = {};
    cfg.gridDim = dim3(1, 1, 1);
    cfg.blockDim = dim3(FIN_THREADS, 1, 1);
    cfg.dynamicSmemBytes = 0;
    cfg.stream = 0;  // same (captured) default stream as the <<<>>> launch
    cudaLaunchAttribute attrs[1];
    attrs[0].id = cudaLaunchAttributeProgrammaticStreamSerialization;
    attrs[0].val.programmaticStreamSerializationAllowed = 1;
    cfg.attrs = attrs;
    cfg.numAttrs = 1;
    cudaLaunchKernelEx(&cfg, cm_finalize_kernel, out);
}

// round 15
// speedup vs baseline: 1.6900x; 1.1600x over previous
#include <cuda_runtime.h>
#include <cuda_device_runtime_api.h>

// Fused confusion-matrix reduction.
//   y_pred, y_true: [16, 3, 512, 512] f32 -> out [B*C, 4] = [tp, tn, fp, fn]
// tp = sum(p*t); fp = sum(p) - tp; fn = sum(t) - tp; tn = N - sum(p) - sum(t) + tp.
//
// Inverted-dependency structure: the tiny kernel (output zeroing) runs FIRST;
// the streaming reduce is PDL-launched so its load stream fully overlaps the
// zero kernel, and each block atomicAdds its 4 transformed partials directly
// into d_out at the end (16-way float REDG per address). No trailing finalize
// kernel, no post-stream flush wait -> the tail is one atomic round.
//
// Streaming config is the R12/R14-measured optimum (14.8us ~= 6.8 TB/s):
// 768 CTAs = 16/slice (single wave), bursts of 8 LDG.128 (OUTER=4 x INNER=4).

#define SLICES 48                       // B*C
#define N_PER_SLICE (512 * 512)         // 262144 elements per slice
#define BLOCKS_PER_SLICE 16
#define THREADS 256
#define NBLOCKS (SLICES * BLOCKS_PER_SLICE)                       // 768
#define VECS_PER_BLOCK (N_PER_SLICE / BLOCKS_PER_SLICE / 4)       // 4096 float4
#define VECS_PER_THREAD (VECS_PER_BLOCK / THREADS)                // 16
#define OUTER 4
#define INNER 4                          // 4 p-vecs + 4 t-vecs per burst
#define N_PER_BLOCK (N_PER_SLICE / BLOCKS_PER_SLICE)              // 16384

__global__ void cm_zero_kernel(float* __restrict__ out, int n) {
    const int i = threadIdx.x;
    if (i < n) out[i] = 0.0f;
}

__global__ __launch_bounds__(THREADS)
void cm_reduce_kernel(const float4* __restrict__ p4, const float4* __restrict__ t4,
                      float* __restrict__ out) {
    const int blk = blockIdx.x;                         // 0 .. 767
    const long base = (long)blk * VECS_PER_BLOCK + threadIdx.x;

    float sp = 0.0f, st = 0.0f, spt = 0.0f;

#pragma unroll 1
    for (int i = 0; i < OUTER; i++) {
        float4 pv[INNER], tv[INNER];
#pragma unroll
        for (int j = 0; j < INNER; j++) {
            const long idx = base + (long)(i * INNER + j) * THREADS;
            pv[j] = __ldg(&p4[idx]);
            tv[j] = __ldg(&t4[idx]);
        }
#pragma unroll
        for (int j = 0; j < INNER; j++) {
            sp  += (pv[j].x + pv[j].y) + (pv[j].z + pv[j].w);
            st  += (tv[j].x + tv[j].y) + (tv[j].z + tv[j].w);
            spt += pv[j].x * tv[j].x + pv[j].y * tv[j].y
                 + pv[j].z * tv[j].z + pv[j].w * tv[j].w;
        }
    }

    // Intra-block tree reduction (warp shuffles + smem).
#pragma unroll
    for (int off = 16; off > 0; off >>= 1) {
        sp  += __shfl_down_sync(0xFFFFFFFFu, sp,  off);
        st  += __shfl_down_sync(0xFFFFFFFFu, st,  off);
        spt += __shfl_down_sync(0xFFFFFFFFu, spt, off);
    }

    __shared__ float sm[3][THREADS / 32];
    const int wid = threadIdx.x >> 5;
    const int lid = threadIdx.x & 31;
    if (lid == 0) {
        sm[0][wid] = sp;
        sm[1][wid] = st;
        sm[2][wid] = spt;
    }
    __syncthreads();

    if (threadIdx.x == 0) {
        float a = 0.0f, b = 0.0f, c = 0.0f;
#pragma unroll
        for (int w = 0; w < THREADS / 32; w++) {
            a += sm[0][w];
            b += sm[1][w];
            c += sm[2][w];
        }
        // Make sure the zero kernel's writes to out are complete & visible.
        // (Long satisfied by now: the zero kernel ran while we streamed.)
        cudaGridDependencySynchronize();

        const int s = blk >> 4;                         // slice index
        const float nchunk = (float)N_PER_BLOCK;
        atomicAdd(&out[s * 4 + 0], c);                  // tp
        atomicAdd(&out[s * 4 + 1], nchunk - a - b + c); // tn
        atomicAdd(&out[s * 4 + 2], a - c);              // fp
        atomicAdd(&out[s * 4 + 3], b - c);              // fn
    }
}

extern "C" void kernel_launch(void* const* d_in, const int* in_sizes, int n_in,
                              void* d_out, int out_size) {
    const float4* p4 = (const float4*)d_in[0];   // y_pred
    const float4* t4 = (const float4*)d_in[1];   // y_true
    float* out = (float*)d_out;

    // Tiny zeroing kernel first.
    cm_zero_kernel<<<1, 256>>>(out, out_size);

    // PDL launch of the streaming reduce: starts immediately, overlapping the
    // zero kernel; blocks only at the grid-dependency sync before its atomics.
    cudaLaunchConfig_t cfg = {};
    cfg.gridDim = dim3(NBLOCKS, 1, 1);
    cfg.blockDim = dim3(THREADS, 1, 1);
    cfg.dynamicSmemBytes = 0;
    cfg.stream = 0;  // same (captured) default stream
    cudaLaunchAttribute attrs[1];
    attrs[0].id = cudaLaunchAttributeProgrammaticStreamSerialization;
    attrs[0].val.programmaticStreamSerializationAllowed = 1;
    cfg.attrs = attrs;
    cfg.numAttrs = 1;
    cudaLaunchKernelEx(&cfg, cm_reduce_kernel, p4, t4, out);
}